// round 6
// baseline (speedup 1.0000x reference)
#include <cuda_runtime.h>
#include <cuda_fp16.h>
#include <math.h>
#include <string.h>

// ---------------------------------------------------------------------------
// SchNet on GB300, round 5: round-4 design with conv occupancy doubled
// (1024 threads/block, 32 warps, 4 atoms x 8-way j split).
// Conv was issue/latency-bound at occ 24.6% / issue 23.8%.
// ---------------------------------------------------------------------------

#define NATOMS 512
#define FDIM   128
#define KKER   301
#define NLAY   3
#define NGRID  576
#define DSCALE 32.0f
#define NWIN   48
#define LOG2F_ 0.6931471805599453f

// scratch (static device globals; no allocations anywhere)
__device__ uint4  g_meta[NATOMS * NATOMS];     // w0..w3 (half) + grid idx
__device__ __half g_tab[NLAY][NGRID * FDIM];
__device__ float  g_h[NATOMS * FDIM];
__device__ __half g_oh[NATOMS * FDIM];

__device__ __forceinline__ float ssp(float x) {
    float ax = fabsf(x);
    return fmaxf(x, 0.0f) + log1pf(expf(-ax)) - LOG2F_;
}

__device__ __forceinline__ __half2 u2h(unsigned u) {
    __half2 h; memcpy(&h, &u, 4); return h;
}

// ---------------------------------------------------------------------------
// 1) prep: pairwise distances -> packed interp meta; plus embedding gather
// ---------------------------------------------------------------------------
__global__ __launch_bounds__(256) void prep_kernel(
    const float* __restrict__ r, const int* __restrict__ x,
    const float* __restrict__ emb)
{
    if (blockIdx.x < 1024) {
        int idx = blockIdx.x * 256 + threadIdx.x;     // N*N pairs
        int i = idx >> 9, j = idx & 511;
        float dx = r[i * 3 + 0] - r[j * 3 + 0];
        float dy = r[i * 3 + 1] - r[j * 3 + 1];
        float dz = r[i * 3 + 2] - r[j * 3 + 2];
        float d = sqrtf(dx * dx + dy * dy + dz * dz);
        float t = fminf(d * DSCALE + 1.0f, (float)(NGRID - 4) + 0.999f);
        float gf = floorf(t);
        int   g  = (int)gf;
        float u  = t - gf;
        float um1 = u - 1.0f, um2 = u - 2.0f, up1 = u + 1.0f;
        float w0 = -u * um1 * um2 * (1.0f / 6.0f);
        float w1 = up1 * um1 * um2 * 0.5f;
        float w2 = -up1 * u * um2 * 0.5f;
        float w3 = up1 * u * um1 * (1.0f / 6.0f);
        __half2 h01 = __floats2half2_rn(w0, w1);
        __half2 h23 = __floats2half2_rn(w2, w3);
        uint4 pk;
        memcpy(&pk.x, &h01, 4);
        memcpy(&pk.y, &h23, 4);
        pk.z = (unsigned)g;
        pk.w = 0;
        g_meta[idx] = pk;
    } else {
        int idx = (blockIdx.x - 1024) * 256 + threadIdx.x;  // N*F elements
        int a = idx >> 7;
        g_h[idx] = emb[x[a] * FDIM + (idx & 127)];
    }
}

// ---------------------------------------------------------------------------
// 2) filter tables (fp16 output). 4 grid points / block, 128 threads.
// ---------------------------------------------------------------------------
__global__ __launch_bounds__(128) void table_kernel(
    const float* __restrict__ cf_W1, const float* __restrict__ cf_b1,
    const float* __restrict__ cf_W2, const float* __restrict__ cf_b2)
{
    int l  = blockIdx.y;
    int i0 = blockIdx.x * 4;
    int tid = threadIdx.x;

    __shared__ float e_s[4][NWIN];
    __shared__ int   k0_s[4];
    __shared__ float w1_s[4][FDIM];

    if (tid < 4) {
        float d = (float)(i0 + tid - 1) * (1.0f / DSCALE);
        int k0 = (int)ceilf((d - 2.0f) * 10.0f);
        k0 = max(0, min(KKER - NWIN, k0));
        k0_s[tid] = k0;
    }
    __syncthreads();

    for (int idx = tid; idx < 4 * NWIN; idx += 128) {
        int p = idx / NWIN, kk = idx - p * NWIN;
        float d = (float)(i0 + p - 1) * (1.0f / DSCALE);
        float c = (float)(k0_s[p] + kk) * 0.1f;
        float del = d - c;
        e_s[p][kk] = expf(-10.0f * del * del);
    }
    __syncthreads();

    const float* W1l = cf_W1 + (size_t)l * KKER * FDIM;
    float b1v = cf_b1[l * FDIM + tid];
    float a0 = b1v, a1 = b1v, a2 = b1v, a3 = b1v;
    for (int kk = 0; kk < NWIN; kk++) {
        a0 += e_s[0][kk] * W1l[(k0_s[0] + kk) * FDIM + tid];
        a1 += e_s[1][kk] * W1l[(k0_s[1] + kk) * FDIM + tid];
        a2 += e_s[2][kk] * W1l[(k0_s[2] + kk) * FDIM + tid];
        a3 += e_s[3][kk] * W1l[(k0_s[3] + kk) * FDIM + tid];
    }
    w1_s[0][tid] = ssp(a0);
    w1_s[1][tid] = ssp(a1);
    w1_s[2][tid] = ssp(a2);
    w1_s[3][tid] = ssp(a3);
    __syncthreads();

    const float* W2l = cf_W2 + (size_t)l * FDIM * FDIM;
    float b2v = cf_b2[l * FDIM + tid];
    float c0 = b2v, c1 = b2v, c2 = b2v, c3 = b2v;
    for (int k = 0; k < FDIM; k++) {
        float wv = W2l[k * FDIM + tid];
        c0 += w1_s[0][k] * wv;
        c1 += w1_s[1][k] * wv;
        c2 += w1_s[2][k] * wv;
        c3 += w1_s[3][k] * wv;
    }
    g_tab[l][(i0 + 0) * FDIM + tid] = __float2half_rn(ssp(c0));
    g_tab[l][(i0 + 1) * FDIM + tid] = __float2half_rn(ssp(c1));
    g_tab[l][(i0 + 2) * FDIM + tid] = __float2half_rn(ssp(c2));
    g_tab[l][(i0 + 3) * FDIM + tid] = __float2half_rn(ssp(c3));
}

// ---------------------------------------------------------------------------
// 3) atom-wise linear: o = h @ W + b (fp32 compute, fp16 store).
// ---------------------------------------------------------------------------
__global__ __launch_bounds__(256) void aw_kernel(
    const float* __restrict__ W, const float* __restrict__ b)
{
    __shared__ float h_sh[4][FDIM];
    __shared__ float part[8][FDIM];
    int tid = threadIdx.x;
    int i0 = blockIdx.x * 4;
    for (int idx = tid; idx < 4 * FDIM; idx += 256)
        h_sh[idx >> 7][idx & 127] = g_h[i0 * FDIM + idx];
    __syncthreads();

    int w = tid >> 5, lane = tid & 31;
    int a = w >> 1, kh = w & 1;
    const float4* Wr = (const float4*)W;
    float4 acc = make_float4(0.f, 0.f, 0.f, 0.f);
    int kbase = kh * 64;
#pragma unroll 8
    for (int kk = 0; kk < 64; kk++) {
        int k = kbase + kk;
        float4 wv = Wr[k * 32 + lane];
        float hv = h_sh[a][k];
        acc.x += hv * wv.x;
        acc.y += hv * wv.y;
        acc.z += hv * wv.z;
        acc.w += hv * wv.w;
    }
    ((float4*)part[w])[lane] = acc;
    __syncthreads();

    for (int idx = tid; idx < 4 * FDIM; idx += 256) {
        int a2 = idx >> 7, f = idx & 127;
        float v = part[2 * a2][f] + part[2 * a2 + 1][f] + b[f];
        g_oh[(i0 + a2) * FDIM + f] = __float2half_rn(v);
    }
}

// ---------------------------------------------------------------------------
// 4) fused conv + n-MLP + residual. 128 blocks x 1024 thr (32 warps).
//    4 atoms/block, 8-way j split; table fully in smem, o in 128-j tiles.
//    part/c/c1 alias the o-tile region (dead after conv mainloop).
//    Layout (bytes):
//      [0,147456)        tab_s (576*128 half)
//      [147456,180224)   meta  (2048 uint4)
//      [180224,212992)   o_t   (128*128 half = 32768)   aliased after conv:
//        part: 32*128 float = 16384 @ 180224
//        c   :  4*128 float =  2048 @ 196608
//        c1  :  4*128 float =  2048 @ 198656
//    total = 212992 B
// ---------------------------------------------------------------------------
#define CS_TAB  0
#define CS_META 147456
#define CS_OT   180224
#define CS_TOT  212992

__global__ __launch_bounds__(1024) void conv_fused_kernel(
    const __half* __restrict__ tab,
    const float* __restrict__ nW1, const float* __restrict__ nb1,
    const float* __restrict__ nW2, const float* __restrict__ nb2)
{
    extern __shared__ char cs[];
    __half* tab_s = (__half*)(cs + CS_TAB);
    uint4*  meta  = (uint4*)(cs + CS_META);
    __half* o_t   = (__half*)(cs + CS_OT);
    float*  part  = (float*)(cs + CS_OT);             // alias (after conv)
    float*  c_sh  = (float*)(cs + CS_OT + 16384);     // alias
    float*  c1_sh = (float*)(cs + CS_OT + 18432);     // alias

    int tid = threadIdx.x;
    int i0 = blockIdx.x * 4;

    // stage full filter table (144 KB): 9216 uint4, 9 per thread
    {
        const uint4* src = (const uint4*)tab;
        uint4* dst = (uint4*)tab_s;
#pragma unroll
        for (int k = 0; k < 9; k++)
            dst[tid + 1024 * k] = src[tid + 1024 * k];
    }
    // stage per-pair meta for this block's 4 atoms (32 KB): 2048 uint4
    {
        const uint4* src = g_meta + (size_t)i0 * NATOMS;
#pragma unroll
        for (int k = 0; k < 2; k++)
            meta[tid + 1024 * k] = src[tid + 1024 * k];
    }

    int w = tid >> 5, lane = tid & 31;
    int a = w >> 3, q = w & 7;                        // 4 atoms x 8 j-splits
    const uint4* mrow = meta + a * NATOMS;

    float4 acc = make_float4(0.f, 0.f, 0.f, 0.f);
#pragma unroll
    for (int jt = 0; jt < 4; jt++) {
        int j0 = jt * 128;
        __syncthreads();                 // o_t reuse barrier (also covers staging)
        {
            const uint4* src = (const uint4*)(g_oh + (size_t)j0 * FDIM);
            uint4* dst = (uint4*)o_t;
#pragma unroll
            for (int k = 0; k < 2; k++)
                dst[tid + 1024 * k] = src[tid + 1024 * k];
        }
        __syncthreads();

        int jl0 = q * 16;                // 16 local j's per warp per tile
#pragma unroll 4
        for (int jj = 0; jj < 16; jj++) {
            int jl = jl0 + jj;
            uint4 m = mrow[j0 + jl];
            int g = (int)m.z;
            __half2 hA = u2h(m.x), hB = u2h(m.y);
            __half2 w0 = __half2half2(__low2half(hA));
            __half2 w1 = __half2half2(__high2half(hA));
            __half2 w2 = __half2half2(__low2half(hB));
            __half2 w3 = __half2half2(__high2half(hB));

            const uint2* trow = (const uint2*)(tab_s + (g - 1) * FDIM);
            uint2 q0 = trow[lane];
            uint2 q1 = trow[32 + lane];
            uint2 q2 = trow[64 + lane];
            uint2 q3 = trow[96 + lane];
            uint2 ov = ((const uint2*)(o_t + jl * FDIM))[lane];

            __half2 fA = __hmul2(w0, u2h(q0.x));
            fA = __hfma2(w1, u2h(q1.x), fA);
            fA = __hfma2(w2, u2h(q2.x), fA);
            fA = __hfma2(w3, u2h(q3.x), fA);
            __half2 pA = __hmul2(fA, u2h(ov.x));
            float2 fpA = __half22float2(pA);
            acc.x += fpA.x;
            acc.y += fpA.y;

            __half2 fB = __hmul2(w0, u2h(q0.y));
            fB = __hfma2(w1, u2h(q1.y), fB);
            fB = __hfma2(w2, u2h(q2.y), fB);
            fB = __hfma2(w3, u2h(q3.y), fB);
            __half2 pB = __hmul2(fB, u2h(ov.y));
            float2 fpB = __half22float2(pB);
            acc.z += fpB.x;
            acc.w += fpB.y;
        }
    }
    __syncthreads();                     // o_t dead; part aliases it now
    ((float4*)(part + w * FDIM))[lane] = acc;
    __syncthreads();

    // combine 8 j-splits: c[a][f] (512 work items)
    if (tid < 512) {
        int a2 = tid >> 7, f = tid & 127;
        float s = 0.0f;
#pragma unroll
        for (int k = 0; k < 8; k++)
            s += part[(a2 * 8 + k) * FDIM + f];
        c_sh[tid] = s;
    }
    __syncthreads();

    int f = tid & 127, ap = tid >> 7;
    // n1: c1 = ssp(c @ W1 + b1)
    if (tid < 512) {
        float acc0 = nb1[f];
        const float* r0 = c_sh + ap * FDIM;
#pragma unroll 8
        for (int k = 0; k < FDIM; k++)
            acc0 += r0[k] * nW1[k * FDIM + f];
        c1_sh[ap * FDIM + f] = ssp(acc0);
    }
    __syncthreads();

    // n2 + residual: h += c1 @ W2 + b2
    if (tid < 512) {
        float acc0 = nb2[f];
        const float* r0 = c1_sh + ap * FDIM;
#pragma unroll 8
        for (int k = 0; k < FDIM; k++)
            acc0 += r0[k] * nW2[k * FDIM + f];
        g_h[(i0 + ap) * FDIM + f] += acc0;
    }
}

// ---------------------------------------------------------------------------
// 5) output head: one warp per atom
// ---------------------------------------------------------------------------
__global__ __launch_bounds__(256) void final_kernel(
    const float* __restrict__ W1, const float* __restrict__ b1,
    const float* __restrict__ W2, const float* __restrict__ b2,
    float* __restrict__ out)
{
    int warp = threadIdx.x >> 5, lane = threadIdx.x & 31;
    int i = blockIdx.x * 8 + warp;
    const float* hi = g_h + i * FDIM;
    float acc = b1[lane];
#pragma unroll 8
    for (int k = 0; k < FDIM; k++)
        acc += hi[k] * W1[k * 32 + lane];
    float v = ssp(acc) * W2[lane];
#pragma unroll
    for (int off = 16; off; off >>= 1)
        v += __shfl_xor_sync(0xffffffffu, v, off);
    if (lane == 0) out[i] = v + b2[0];
}

// ---------------------------------------------------------------------------
extern "C" void kernel_launch(void* const* d_in, const int* in_sizes, int n_in,
                              void* d_out, int out_size) {
    const int*   x      = (const int*)  d_in[0];
    const float* r      = (const float*)d_in[1];
    const float* emb    = (const float*)d_in[2];
    const float* aw_W   = (const float*)d_in[3];
    const float* aw_b   = (const float*)d_in[4];
    const float* cf_W1  = (const float*)d_in[5];
    const float* cf_b1  = (const float*)d_in[6];
    const float* cf_W2  = (const float*)d_in[7];
    const float* cf_b2  = (const float*)d_in[8];
    const float* n_W1   = (const float*)d_in[9];
    const float* n_b1   = (const float*)d_in[10];
    const float* n_W2   = (const float*)d_in[11];
    const float* n_b2   = (const float*)d_in[12];
    const float* out_W1 = (const float*)d_in[13];
    const float* out_b1 = (const float*)d_in[14];
    const float* out_W2 = (const float*)d_in[15];
    const float* out_b2 = (const float*)d_in[16];

    __half* p_tab;
    cudaGetSymbolAddress((void**)&p_tab, g_tab);

    cudaFuncSetAttribute(conv_fused_kernel,
                         cudaFuncAttributeMaxDynamicSharedMemorySize, CS_TOT);

    prep_kernel<<<1280, 256>>>(r, x, emb);
    table_kernel<<<dim3(NGRID / 4, NLAY), 128>>>(cf_W1, cf_b1, cf_W2, cf_b2);

    for (int l = 0; l < NLAY; l++) {
        aw_kernel<<<NATOMS / 4, 256>>>(aw_W + (size_t)l * FDIM * FDIM,
                                       aw_b + l * FDIM);
        conv_fused_kernel<<<NATOMS / 4, 1024, CS_TOT>>>(
            p_tab + (size_t)l * NGRID * FDIM,
            n_W1 + (size_t)l * FDIM * FDIM, n_b1 + l * FDIM,
            n_W2 + (size_t)l * FDIM * FDIM, n_b2 + l * FDIM);
    }
    final_kernel<<<NATOMS / 8, 256>>>(out_W1, out_b1, out_W2, out_b2,
                                      (float*)d_out);
}

// round 8
// speedup vs baseline: 1.0121x; 1.0121x over previous
#include <cuda_runtime.h>
#include <cuda_fp16.h>
#include <math.h>
#include <string.h>

// ---------------------------------------------------------------------------
// SchNet on GB300, round 8: software-pipelined conv under the 212992-B
// empirical smem ceiling (R3/R7 container deaths both exceeded it).
// Packed per-pair weights (uint2) + ushort grid idx; broadcast in-loop
// via __half2half2 (ALU pipe, underused). Double-buffered inner loop.
// ---------------------------------------------------------------------------

#define NATOMS 512
#define FDIM   128
#define KKER   301
#define NLAY   3
#define NGRID  576
#define DSCALE 32.0f
#define NWIN   48
#define LOG2F_ 0.6931471805599453f

// scratch (static device globals; no allocations anywhere)
__device__ uint2          g_w4[NATOMS * NATOMS];   // packed half w0..w3
__device__ unsigned short g_gi[NATOMS * NATOMS];   // grid index
__device__ __half         g_tab[NLAY][NGRID * FDIM];
__device__ float          g_h[NATOMS * FDIM];
__device__ __half         g_oh[NATOMS * FDIM];

__device__ __forceinline__ float ssp(float x) {
    float ax = fabsf(x);
    return fmaxf(x, 0.0f) + log1pf(expf(-ax)) - LOG2F_;
}

__device__ __forceinline__ __half2 u2h(unsigned u) {
    __half2 h; memcpy(&h, &u, 4); return h;
}

// ---------------------------------------------------------------------------
// 1) prep: pairwise distances -> packed interp weights + grid idx; embed
// ---------------------------------------------------------------------------
__global__ __launch_bounds__(256) void prep_kernel(
    const float* __restrict__ r, const int* __restrict__ x,
    const float* __restrict__ emb)
{
    if (blockIdx.x < 1024) {
        int idx = blockIdx.x * 256 + threadIdx.x;     // N*N pairs
        int i = idx >> 9, j = idx & 511;
        float dx = r[i * 3 + 0] - r[j * 3 + 0];
        float dy = r[i * 3 + 1] - r[j * 3 + 1];
        float dz = r[i * 3 + 2] - r[j * 3 + 2];
        float d = sqrtf(dx * dx + dy * dy + dz * dz);
        float t = fminf(d * DSCALE + 1.0f, (float)(NGRID - 4) + 0.999f);
        float gf = floorf(t);
        int   g  = (int)gf;
        float u  = t - gf;
        float um1 = u - 1.0f, um2 = u - 2.0f, up1 = u + 1.0f;
        float w0 = -u * um1 * um2 * (1.0f / 6.0f);
        float w1 = up1 * um1 * um2 * 0.5f;
        float w2 = -up1 * u * um2 * 0.5f;
        float w3 = up1 * u * um1 * (1.0f / 6.0f);
        __half2 h01 = __floats2half2_rn(w0, w1);
        __half2 h23 = __floats2half2_rn(w2, w3);
        uint2 pk;
        memcpy(&pk.x, &h01, 4);
        memcpy(&pk.y, &h23, 4);
        g_w4[idx] = pk;
        g_gi[idx] = (unsigned short)g;
    } else {
        int idx = (blockIdx.x - 1024) * 256 + threadIdx.x;  // N*F elements
        int a = idx >> 7;
        g_h[idx] = emb[x[a] * FDIM + (idx & 127)];
    }
}

// ---------------------------------------------------------------------------
// 2) filter tables (fp16 output). 4 grid points / block, 128 threads.
// ---------------------------------------------------------------------------
__global__ __launch_bounds__(128) void table_kernel(
    const float* __restrict__ cf_W1, const float* __restrict__ cf_b1,
    const float* __restrict__ cf_W2, const float* __restrict__ cf_b2)
{
    int l  = blockIdx.y;
    int i0 = blockIdx.x * 4;
    int tid = threadIdx.x;

    __shared__ float e_s[4][NWIN];
    __shared__ int   k0_s[4];
    __shared__ float w1_s[4][FDIM];

    if (tid < 4) {
        float d = (float)(i0 + tid - 1) * (1.0f / DSCALE);
        int k0 = (int)ceilf((d - 2.0f) * 10.0f);
        k0 = max(0, min(KKER - NWIN, k0));
        k0_s[tid] = k0;
    }
    __syncthreads();

    for (int idx = tid; idx < 4 * NWIN; idx += 128) {
        int p = idx / NWIN, kk = idx - p * NWIN;
        float d = (float)(i0 + p - 1) * (1.0f / DSCALE);
        float c = (float)(k0_s[p] + kk) * 0.1f;
        float del = d - c;
        e_s[p][kk] = expf(-10.0f * del * del);
    }
    __syncthreads();

    const float* W1l = cf_W1 + (size_t)l * KKER * FDIM;
    float b1v = cf_b1[l * FDIM + tid];
    float a0 = b1v, a1 = b1v, a2 = b1v, a3 = b1v;
    for (int kk = 0; kk < NWIN; kk++) {
        a0 += e_s[0][kk] * W1l[(k0_s[0] + kk) * FDIM + tid];
        a1 += e_s[1][kk] * W1l[(k0_s[1] + kk) * FDIM + tid];
        a2 += e_s[2][kk] * W1l[(k0_s[2] + kk) * FDIM + tid];
        a3 += e_s[3][kk] * W1l[(k0_s[3] + kk) * FDIM + tid];
    }
    w1_s[0][tid] = ssp(a0);
    w1_s[1][tid] = ssp(a1);
    w1_s[2][tid] = ssp(a2);
    w1_s[3][tid] = ssp(a3);
    __syncthreads();

    const float* W2l = cf_W2 + (size_t)l * FDIM * FDIM;
    float b2v = cf_b2[l * FDIM + tid];
    float c0 = b2v, c1 = b2v, c2 = b2v, c3 = b2v;
    for (int k = 0; k < FDIM; k++) {
        float wv = W2l[k * FDIM + tid];
        c0 += w1_s[0][k] * wv;
        c1 += w1_s[1][k] * wv;
        c2 += w1_s[2][k] * wv;
        c3 += w1_s[3][k] * wv;
    }
    g_tab[l][(i0 + 0) * FDIM + tid] = __float2half_rn(ssp(c0));
    g_tab[l][(i0 + 1) * FDIM + tid] = __float2half_rn(ssp(c1));
    g_tab[l][(i0 + 2) * FDIM + tid] = __float2half_rn(ssp(c2));
    g_tab[l][(i0 + 3) * FDIM + tid] = __float2half_rn(ssp(c3));
}

// ---------------------------------------------------------------------------
// 3) atom-wise linear: o = h @ W + b (fp32 compute, fp16 store).
// ---------------------------------------------------------------------------
__global__ __launch_bounds__(256) void aw_kernel(
    const float* __restrict__ W, const float* __restrict__ b)
{
    __shared__ float h_sh[4][FDIM];
    __shared__ float part[8][FDIM];
    int tid = threadIdx.x;
    int i0 = blockIdx.x * 4;
    for (int idx = tid; idx < 4 * FDIM; idx += 256)
        h_sh[idx >> 7][idx & 127] = g_h[i0 * FDIM + idx];
    __syncthreads();

    int w = tid >> 5, lane = tid & 31;
    int a = w >> 1, kh = w & 1;
    const float4* Wr = (const float4*)W;
    float4 acc = make_float4(0.f, 0.f, 0.f, 0.f);
    int kbase = kh * 64;
#pragma unroll 8
    for (int kk = 0; kk < 64; kk++) {
        int k = kbase + kk;
        float4 wv = Wr[k * 32 + lane];
        float hv = h_sh[a][k];
        acc.x += hv * wv.x;
        acc.y += hv * wv.y;
        acc.z += hv * wv.z;
        acc.w += hv * wv.w;
    }
    ((float4*)part[w])[lane] = acc;
    __syncthreads();

    for (int idx = tid; idx < 4 * FDIM; idx += 256) {
        int a2 = idx >> 7, f = idx & 127;
        float v = part[2 * a2][f] + part[2 * a2 + 1][f] + b[f];
        g_oh[(i0 + a2) * FDIM + f] = __float2half_rn(v);
    }
}

// ---------------------------------------------------------------------------
// 4) fused conv + n-MLP + residual. 128 blocks x 1024 thr (32 warps).
//    4 atoms/block, 8-way j split; table fully in smem, o in 128-j tiles.
//    Explicit double-buffered software pipeline in the inner loop.
//    Layout (bytes):
//      [0,147456)        tab_s (576*128 half)
//      [147456,163840)   w4    (2048 uint2, packed weights)
//      [163840,167936)   gi    (2048 ushort)
//      [167936,200704)   o_t   (128*128 half = 32768)  aliased after conv:
//        part: 32*128 float = 16384 @ 167936
//        c   :  4*128 float =  2048 @ 184320
//        c1  :  4*128 float =  2048 @ 186368
//    total = 200704 B  (< 212992 empirical ceiling)
// ---------------------------------------------------------------------------
#define CS_TAB  0
#define CS_W4   147456
#define CS_GI   163840
#define CS_OT   167936
#define CS_TOT  200704

__global__ __launch_bounds__(1024) void conv_fused_kernel(
    const __half* __restrict__ tab,
    const float* __restrict__ nW1, const float* __restrict__ nb1,
    const float* __restrict__ nW2, const float* __restrict__ nb2)
{
    extern __shared__ char cs[];
    __half*         tab_s = (__half*)(cs + CS_TAB);
    uint2*          w4    = (uint2*)(cs + CS_W4);
    unsigned short* gi    = (unsigned short*)(cs + CS_GI);
    __half*         o_t   = (__half*)(cs + CS_OT);
    float*          part  = (float*)(cs + CS_OT);             // alias
    float*          c_sh  = (float*)(cs + CS_OT + 16384);     // alias
    float*          c1_sh = (float*)(cs + CS_OT + 18432);     // alias

    int tid = threadIdx.x;
    int i0 = blockIdx.x * 4;

    // stage full filter table (144 KB): 9216 uint4, 9 per thread
    {
        const uint4* src = (const uint4*)tab;
        uint4* dst = (uint4*)tab_s;
#pragma unroll
        for (int k = 0; k < 9; k++)
            dst[tid + 1024 * k] = src[tid + 1024 * k];
    }
    // stage packed weights (16 KB = 1024 uint4) + grid idx (4 KB = 1024 uint)
    {
        ((uint4*)w4)[tid] = ((const uint4*)(g_w4 + (size_t)i0 * NATOMS))[tid];
        ((unsigned*)gi)[tid] =
            ((const unsigned*)(g_gi + (size_t)i0 * NATOMS))[tid];
    }

    int w = tid >> 5, lane = tid & 31;
    int a = w >> 3, q = w & 7;                        // 4 atoms x 8 j-splits
    const uint2*          wrow = w4 + a * NATOMS;
    const unsigned short* grow = gi + a * NATOMS;

    float4 acc = make_float4(0.f, 0.f, 0.f, 0.f);
#pragma unroll
    for (int jt = 0; jt < 4; jt++) {
        int j0 = jt * 128;
        __syncthreads();                 // o_t reuse barrier (also covers staging)
        {
            const uint4* src = (const uint4*)(g_oh + (size_t)j0 * FDIM);
            uint4* dst = (uint4*)o_t;
#pragma unroll
            for (int k = 0; k < 2; k++)
                dst[tid + 1024 * k] = src[tid + 1024 * k];
        }
        __syncthreads();

        int jb = j0 + q * 16;            // global meta idx base for this warp
        int jl = q * 16;                 // local o_t row base

        // ---- software-pipelined inner loop (double-buffered) ----
        uint2 wc = wrow[jb];
        int   gc = (int)grow[jb];
        const uint2* trow = (const uint2*)(tab_s + (gc - 1) * FDIM);
        uint2 t0 = trow[lane];
        uint2 t1 = trow[32 + lane];
        uint2 t2 = trow[64 + lane];
        uint2 t3 = trow[96 + lane];
        uint2 ov = ((const uint2*)(o_t + jl * FDIM))[lane];

#pragma unroll
        for (int jj = 0; jj < 16; jj++) {
            uint2 wn; int gn;
            uint2 t0n, t1n, t2n, t3n, ovn;
            if (jj < 15) {
                wn = wrow[jb + jj + 1];
                gn = (int)grow[jb + jj + 1];
                const uint2* tr = (const uint2*)(tab_s + (gn - 1) * FDIM);
                t0n = tr[lane];
                t1n = tr[32 + lane];
                t2n = tr[64 + lane];
                t3n = tr[96 + lane];
                ovn = ((const uint2*)(o_t + (jl + jj + 1) * FDIM))[lane];
            }

            __half2 hA = u2h(wc.x), hB = u2h(wc.y);
            __half2 w0 = __half2half2(__low2half(hA));
            __half2 w1 = __half2half2(__high2half(hA));
            __half2 w2 = __half2half2(__low2half(hB));
            __half2 w3 = __half2half2(__high2half(hB));

            // tree-shaped filter eval, depth 3
            __half2 pAa = __hfma2(w1, u2h(t1.x), __hmul2(w0, u2h(t0.x)));
            __half2 pAb = __hfma2(w3, u2h(t3.x), __hmul2(w2, u2h(t2.x)));
            __half2 fA  = __hadd2(pAa, pAb);
            __half2 mA  = __hmul2(fA, u2h(ov.x));
            float2 fpA = __half22float2(mA);
            acc.x += fpA.x;
            acc.y += fpA.y;

            __half2 pBa = __hfma2(w1, u2h(t1.y), __hmul2(w0, u2h(t0.y)));
            __half2 pBb = __hfma2(w3, u2h(t3.y), __hmul2(w2, u2h(t2.y)));
            __half2 fB  = __hadd2(pBa, pBb);
            __half2 mB  = __hmul2(fB, u2h(ov.y));
            float2 fpB = __half22float2(mB);
            acc.z += fpB.x;
            acc.w += fpB.y;

            if (jj < 15) {
                wc = wn; gc = gn;
                t0 = t0n; t1 = t1n; t2 = t2n; t3 = t3n;
                ov = ovn;
            }
        }
    }
    __syncthreads();                     // o_t dead; part aliases it now
    ((float4*)(part + w * FDIM))[lane] = acc;
    __syncthreads();

    // combine 8 j-splits: c[a][f] (512 work items)
    if (tid < 512) {
        int a2 = tid >> 7, f = tid & 127;
        float s = 0.0f;
#pragma unroll
        for (int k = 0; k < 8; k++)
            s += part[(a2 * 8 + k) * FDIM + f];
        c_sh[tid] = s;
    }
    __syncthreads();

    int f = tid & 127, ap = tid >> 7;
    // n1: c1 = ssp(c @ W1 + b1)
    if (tid < 512) {
        float acc0 = nb1[f];
        const float* r0 = c_sh + ap * FDIM;
#pragma unroll 8
        for (int k = 0; k < FDIM; k++)
            acc0 += r0[k] * nW1[k * FDIM + f];
        c1_sh[ap * FDIM + f] = ssp(acc0);
    }
    __syncthreads();

    // n2 + residual: h += c1 @ W2 + b2
    if (tid < 512) {
        float acc0 = nb2[f];
        const float* r0 = c1_sh + ap * FDIM;
#pragma unroll 8
        for (int k = 0; k < FDIM; k++)
            acc0 += r0[k] * nW2[k * FDIM + f];
        g_h[(i0 + ap) * FDIM + f] += acc0;
    }
}

// ---------------------------------------------------------------------------
// 5) output head: one warp per atom
// ---------------------------------------------------------------------------
__global__ __launch_bounds__(256) void final_kernel(
    const float* __restrict__ W1, const float* __restrict__ b1,
    const float* __restrict__ W2, const float* __restrict__ b2,
    float* __restrict__ out)
{
    int warp = threadIdx.x >> 5, lane = threadIdx.x & 31;
    int i = blockIdx.x * 8 + warp;
    const float* hi = g_h + i * FDIM;
    float acc = b1[lane];
#pragma unroll 8
    for (int k = 0; k < FDIM; k++)
        acc += hi[k] * W1[k * 32 + lane];
    float v = ssp(acc) * W2[lane];
#pragma unroll
    for (int off = 16; off; off >>= 1)
        v += __shfl_xor_sync(0xffffffffu, v, off);
    if (lane == 0) out[i] = v + b2[0];
}

// ---------------------------------------------------------------------------
extern "C" void kernel_launch(void* const* d_in, const int* in_sizes, int n_in,
                              void* d_out, int out_size) {
    const int*   x      = (const int*)  d_in[0];
    const float* r      = (const float*)d_in[1];
    const float* emb    = (const float*)d_in[2];
    const float* aw_W   = (const float*)d_in[3];
    const float* aw_b   = (const float*)d_in[4];
    const float* cf_W1  = (const float*)d_in[5];
    const float* cf_b1  = (const float*)d_in[6];
    const float* cf_W2  = (const float*)d_in[7];
    const float* cf_b2  = (const float*)d_in[8];
    const float* n_W1   = (const float*)d_in[9];
    const float* n_b1   = (const float*)d_in[10];
    const float* n_W2   = (const float*)d_in[11];
    const float* n_b2   = (const float*)d_in[12];
    const float* out_W1 = (const float*)d_in[13];
    const float* out_b1 = (const float*)d_in[14];
    const float* out_W2 = (const float*)d_in[15];
    const float* out_b2 = (const float*)d_in[16];

    __half* p_tab;
    cudaGetSymbolAddress((void**)&p_tab, g_tab);

    cudaFuncSetAttribute(conv_fused_kernel,
                         cudaFuncAttributeMaxDynamicSharedMemorySize, CS_TOT);

    prep_kernel<<<1280, 256>>>(r, x, emb);
    table_kernel<<<dim3(NGRID / 4, NLAY), 128>>>(cf_W1, cf_b1, cf_W2, cf_b2);

    for (int l = 0; l < NLAY; l++) {
        aw_kernel<<<NATOMS / 4, 256>>>(aw_W + (size_t)l * FDIM * FDIM,
                                       aw_b + l * FDIM);
        conv_fused_kernel<<<NATOMS / 4, 1024, CS_TOT>>>(
            p_tab + (size_t)l * NGRID * FDIM,
            n_W1 + (size_t)l * FDIM * FDIM, n_b1 + l * FDIM,
            n_W2 + (size_t)l * FDIM * FDIM, n_b2 + l * FDIM);
    }
    final_kernel<<<NATOMS / 8, 256>>>(out_W1, out_b1, out_W2, out_b2,
                                      (float*)d_out);
}